// round 3
// baseline (speedup 1.0000x reference)
#include <cuda_runtime.h>
#include <math.h>

#define DIM 256
#define NH 4
#define HC 64
#define NTOK 49
#define NB 4096

// Standardized weights/biases (written once per launch by std_kernel).
__device__ __align__(16) float g_W[5][DIM * DIM];
__device__ float g_b[5][DIM];

// ---------------------------------------------------------------------------
// Kernel 0: weight standardization.
//   blocks [0, 5*256): one block per (matrix m, row): per-head (64-col group)
//   normalize: (w - mean)/(std * sqrt(256)).
//   blocks [1280, 1285): biases, same per-head normalization.
// ---------------------------------------------------------------------------
__global__ __launch_bounds__(256) void std_kernel(
    const float* __restrict__ qw, const float* __restrict__ qb,
    const float* __restrict__ kw, const float* __restrict__ kb,
    const float* __restrict__ vw, const float* __restrict__ vb,
    const float* __restrict__ fiw, const float* __restrict__ fib,
    const float* __restrict__ fow, const float* __restrict__ fob)
{
    const float* wptr[5] = {qw, kw, vw, fiw, fow};
    const float* bptr[5] = {qb, kb, vb, fib, fob};

    __shared__ float s_sum[8];
    __shared__ float s_sq[8];

    int bx = blockIdx.x;
    int t  = threadIdx.x;

    float val;
    float* outp;
    if (bx < 5 * DIM) {
        int m = bx >> 8;
        int row = bx & 255;
        val  = wptr[m][row * DIM + t];
        outp = &g_W[m][row * DIM + t];
    } else {
        int m = bx - 5 * DIM;
        val  = bptr[m][t];
        outp = &g_b[m][t];
    }

    float s = val, q = val * val;
    #pragma unroll
    for (int o = 16; o > 0; o >>= 1) {
        s += __shfl_xor_sync(0xFFFFFFFFu, s, o);
        q += __shfl_xor_sync(0xFFFFFFFFu, q, o);
    }
    int w = t >> 5;
    if ((t & 31) == 0) { s_sum[w] = s; s_sq[w] = q; }
    __syncthreads();

    int h = t >> 6;  // head = group of 64 cols = warps 2h, 2h+1
    float sum = s_sum[2 * h] + s_sum[2 * h + 1];
    float sq  = s_sq [2 * h] + s_sq [2 * h + 1];
    float mean = sum * (1.0f / 64.0f);
    float var  = fmaxf(sq * (1.0f / 64.0f) - mean * mean, 0.0f);
    float sd   = sqrtf(var);
    *outp = (val - mean) / (sd * 16.0f);   // sqrt(DIM) = 16
}

// ---------------------------------------------------------------------------
// Main kernel: one CTA per batch sample. 256 threads.
// smem layout (floats):
//   AT [256][57]  : activations TRANSPOSED: AT[c*57 + r]    (stride 57: odd)
//   Qb [49][257]  : Q
//   KV [49][257]  : K, then reused for V
//   S  [4][56][49]: attention scores / probs per head (rows padded to 56)
//
// GEMM thread mapping: tr=tid>>5 (rows tr+8j, j<7), ct=tid&31,
// columns col(cc) = 128*(cc>>2) + 4*ct + (cc&3)  -> two float4 groups.
// ---------------------------------------------------------------------------
#define AT_STRIDE 57
#define QK_STRIDE 257
#define S_HSTRIDE (56 * 49)

#define AT_FLOATS (256 * AT_STRIDE)
#define QK_FLOATS (49 * QK_STRIDE)
#define S_FLOATS  (4 * 56 * 49)
#define SMEM_FLOATS (AT_FLOATS + 2 * QK_FLOATS + S_FLOATS)

#define COL(cc) (128 * ((cc) >> 2) + 4 * ct + ((cc) & 3))

__device__ __forceinline__ void gemm_acc(
    const float* __restrict__ AT, const float* __restrict__ W,
    float acc[7][8], int tr, int ct)
{
    #pragma unroll
    for (int j = 0; j < 7; j++)
        #pragma unroll
        for (int cc = 0; cc < 8; cc++) acc[j][cc] = 0.0f;

    const float4* __restrict__ W4 = (const float4*)W;   // 64 float4 per row

    #pragma unroll 4
    for (int k = 0; k < DIM; k++) {
        float xv[7];
        #pragma unroll
        for (int j = 0; j < 7; j++)
            xv[j] = AT[k * AT_STRIDE + tr + 8 * j];   // warp-broadcast LDS
        float4 wa = __ldg(&W4[k * 64 + ct]);          // cols 4ct..4ct+3
        float4 wb = __ldg(&W4[k * 64 + 32 + ct]);     // cols 128+4ct..
        float wv[8] = {wa.x, wa.y, wa.z, wa.w, wb.x, wb.y, wb.z, wb.w};
        #pragma unroll
        for (int j = 0; j < 7; j++)
            #pragma unroll
            for (int cc = 0; cc < 8; cc++)
                acc[j][cc] = fmaf(xv[j], wv[cc], acc[j][cc]);
    }
}

__global__ __launch_bounds__(256, 1) void irmb_kernel(
    const float* __restrict__ x, float* __restrict__ out)
{
    extern __shared__ float sm[];
    float* AT = sm;
    float* Qb = sm + AT_FLOATS;
    float* KV = Qb + QK_FLOATS;
    float* S  = KV + QK_FLOATS;

    const int b   = blockIdx.x;
    const int tid = threadIdx.x;
    const int ct  = tid & 31;
    const int tr  = tid >> 5;

    const float* xb = x + (size_t)b * (NTOK * DIM);
    float* ob = out + (size_t)b * (NTOK * DIM);

    // ---- load x transposed into AT ----
    for (int i = tid; i < NTOK * DIM; i += 256) {
        int r = i >> 8, c = i & 255;
        AT[c * AT_STRIDE + r] = xb[i];
    }
    __syncthreads();

    float acc[7][8];

    // ---- Q = x @ Wq' + bq' ----
    gemm_acc(AT, g_W[0], acc, tr, ct);
    #pragma unroll
    for (int j = 0; j < 7; j++) {
        int r = tr + 8 * j;
        if (r < NTOK) {
            #pragma unroll
            for (int cc = 0; cc < 8; cc++) {
                int c = COL(cc);
                Qb[r * QK_STRIDE + c] = acc[j][cc] + g_b[0][c];
            }
        }
    }

    // ---- K = x @ Wk' + bk' ----
    gemm_acc(AT, g_W[1], acc, tr, ct);
    #pragma unroll
    for (int j = 0; j < 7; j++) {
        int r = tr + 8 * j;
        if (r < NTOK) {
            #pragma unroll
            for (int cc = 0; cc < 8; cc++) {
                int c = COL(cc);
                KV[r * QK_STRIDE + c] = acc[j][cc] + g_b[1][c];
            }
        }
    }
    __syncthreads();

    // ---- scores S[h][q][kk] = SCALE * <Q[q],K[kk]> ----
    const float SCALE = 0.125f;  // 64^-0.5
    for (int idx = tid; idx < NH * NTOK * NTOK; idx += 256) {
        int h  = idx / (NTOK * NTOK);
        int r2 = idx - h * (NTOK * NTOK);
        int qr = r2 / NTOK;
        int kk = r2 - qr * NTOK;
        const float* qp = &Qb[qr * QK_STRIDE + h * HC];
        const float* kp = &KV[kk * QK_STRIDE + h * HC];
        float a = 0.0f;
        #pragma unroll 16
        for (int c = 0; c < HC; c++) a = fmaf(qp[c], kp[c], a);
        S[h * S_HSTRIDE + qr * NTOK + kk] = a * SCALE;
    }
    __syncthreads();

    // ---- softmax over kk, in place (196 rows) ----
    if (tid < NH * NTOK) {
        int h = tid / NTOK, qr = tid - h * NTOK;
        float* row = &S[h * S_HSTRIDE + qr * NTOK];
        float m = -1e30f;
        for (int kk = 0; kk < NTOK; kk++) m = fmaxf(m, row[kk]);
        float sumv = 0.0f;
        for (int kk = 0; kk < NTOK; kk++) {
            float e = expf(row[kk] - m);
            row[kk] = e;
            sumv += e;
        }
        float inv = 1.0f / sumv;
        for (int kk = 0; kk < NTOK; kk++) row[kk] *= inv;
    }
    __syncthreads();

    // ---- V = (x @ Wv' + bv') * 0.1 + x * 0.95, into KV buffer ----
    gemm_acc(AT, g_W[2], acc, tr, ct);
    #pragma unroll
    for (int j = 0; j < 7; j++) {
        int r = tr + 8 * j;
        if (r < NTOK) {
            #pragma unroll
            for (int cc = 0; cc < 8; cc++) {
                int c = COL(cc);
                float v = acc[j][cc] + g_b[2][c];
                KV[r * QK_STRIDE + c] = v * 0.1f + AT[c * AT_STRIDE + r] * 0.95f;
            }
        }
    }
    __syncthreads();

    // ---- O = P @ V ; xnew = O*0.1 + V*0.95 ; write xnew transposed to AT ----
    {
        float acc2[7][8];
        #pragma unroll
        for (int j = 0; j < 7; j++)
            #pragma unroll
            for (int cc = 0; cc < 8; cc++) acc2[j][cc] = 0.0f;

        const int hsel = ct >> 4;   // head = 2*(cc>>2) + (ct>=16)
        for (int kk = 0; kk < NTOK; kk++) {
            float pv[4][7];
            #pragma unroll
            for (int h = 0; h < 4; h++)
                #pragma unroll
                for (int j = 0; j < 7; j++)
                    pv[h][j] = S[h * S_HSTRIDE + (tr + 8 * j) * NTOK + kk]; // padded rows: in-bounds
            float vv[8];
            #pragma unroll
            for (int cc = 0; cc < 8; cc++)
                vv[cc] = KV[kk * QK_STRIDE + COL(cc)];
            #pragma unroll
            for (int j = 0; j < 7; j++)
                #pragma unroll
                for (int cc = 0; cc < 8; cc++)
                    acc2[j][cc] = fmaf(pv[2 * (cc >> 2) + hsel][j], vv[cc], acc2[j][cc]);
        }
        #pragma unroll
        for (int j = 0; j < 7; j++) {
            int r = tr + 8 * j;
            if (r < NTOK) {
                #pragma unroll
                for (int cc = 0; cc < 8; cc++) {
                    int c = COL(cc);
                    float xnew = acc2[j][cc] * 0.1f + KV[r * QK_STRIDE + c] * 0.95f;
                    AT[c * AT_STRIDE + r] = xnew;
                }
            }
        }
    }
    __syncthreads();

    // ---- FFN in: t1 = x@Wfi'+b ; t2 = t1*0.1 + x*0.95 ;
    //      t3 = (sigmoid(t2)-0.5)*0.1 + t2*0.95 ----
    gemm_acc(AT, g_W[3], acc, tr, ct);
    #pragma unroll
    for (int j = 0; j < 7; j++) {
        int r = tr + 8 * j;
        if (r < NTOK) {
            #pragma unroll
            for (int cc = 0; cc < 8; cc++) {
                int c = COL(cc);
                float t1 = acc[j][cc] + g_b[3][c];
                float t2 = t1 * 0.1f + AT[c * AT_STRIDE + r] * 0.95f;
                float sg = 1.0f / (1.0f + expf(-t2));
                acc[j][cc] = (sg - 0.5f) * 0.1f + t2 * 0.95f;   // t3 in regs
            }
        }
    }
    __syncthreads();   // all reads of old AT complete
    #pragma unroll
    for (int j = 0; j < 7; j++) {
        int r = tr + 8 * j;
        if (r < NTOK) {
            #pragma unroll
            for (int cc = 0; cc < 8; cc++)
                AT[COL(cc) * AT_STRIDE + r] = acc[j][cc];
        }
    }
    __syncthreads();

    // ---- FFN out: t4 = t3@Wfo'+b ; out = t4*0.1 + t3*0.95 ----
    gemm_acc(AT, g_W[4], acc, tr, ct);
    #pragma unroll
    for (int j = 0; j < 7; j++) {
        int r = tr + 8 * j;
        if (r < NTOK) {
            #pragma unroll
            for (int g = 0; g < 2; g++) {
                int c0 = 128 * g + 4 * ct;
                float4 o4;
                o4.x = (acc[j][4*g+0] + g_b[4][c0+0]) * 0.1f + AT[(c0+0) * AT_STRIDE + r] * 0.95f;
                o4.y = (acc[j][4*g+1] + g_b[4][c0+1]) * 0.1f + AT[(c0+1) * AT_STRIDE + r] * 0.95f;
                o4.z = (acc[j][4*g+2] + g_b[4][c0+2]) * 0.1f + AT[(c0+2) * AT_STRIDE + r] * 0.95f;
                o4.w = (acc[j][4*g+3] + g_b[4][c0+3]) * 0.1f + AT[(c0+3) * AT_STRIDE + r] * 0.95f;
                *reinterpret_cast<float4*>(&ob[r * DIM + c0]) = o4;
            }
        }
    }
}

// ---------------------------------------------------------------------------
extern "C" void kernel_launch(void* const* d_in, const int* in_sizes, int n_in,
                              void* d_out, int out_size)
{
    const float* x = (const float*)d_in[0];

    std_kernel<<<5 * DIM + 5, 256>>>(
        (const float*)d_in[1], (const float*)d_in[2],
        (const float*)d_in[3], (const float*)d_in[4],
        (const float*)d_in[5], (const float*)d_in[6],
        (const float*)d_in[7], (const float*)d_in[8],
        (const float*)d_in[9], (const float*)d_in[10]);

    size_t smem = (size_t)SMEM_FLOATS * sizeof(float);   // ~203 KB
    cudaFuncSetAttribute(irmb_kernel,
                         cudaFuncAttributeMaxDynamicSharedMemorySize, (int)smem);
    irmb_kernel<<<NB, 256, smem>>>(x, (float*)d_out);
}

// round 5
// speedup vs baseline: 4.2561x; 4.2561x over previous
#include <cuda_runtime.h>
#include <cuda_bf16.h>
#include <math.h>
#include <stdint.h>

#define DIM  256
#define NH   4
#define HC   64
#define NTOK 49
#define NB   4096

// Transposed standardized weights bf16: g_Wbf[m][c*256+k]; biases fp32.
__device__ __align__(16) __nv_bfloat16 g_Wbf[5][DIM * DIM];
__device__ float g_b[5][DIM];

// ---------------------------------------------------------------------------
// Prologue: weight standardization -> transposed bf16
// ---------------------------------------------------------------------------
__global__ __launch_bounds__(256) void std_kernel(
    const float* __restrict__ qw, const float* __restrict__ qb,
    const float* __restrict__ kw, const float* __restrict__ kb,
    const float* __restrict__ vw, const float* __restrict__ vb,
    const float* __restrict__ fiw, const float* __restrict__ fib,
    const float* __restrict__ fow, const float* __restrict__ fob)
{
    const float* wptr[5] = {qw, kw, vw, fiw, fow};
    const float* bptr[5] = {qb, kb, vb, fib, fob};
    __shared__ float s_sum[8], s_sq[8];
    int bx = blockIdx.x, t = threadIdx.x;

    float val;
    if (bx < 5 * DIM) val = wptr[bx >> 8][(bx & 255) * DIM + t];
    else              val = bptr[bx - 5 * DIM][t];

    float s = val, q = val * val;
    #pragma unroll
    for (int o = 16; o > 0; o >>= 1) {
        s += __shfl_xor_sync(0xFFFFFFFFu, s, o);
        q += __shfl_xor_sync(0xFFFFFFFFu, q, o);
    }
    if ((t & 31) == 0) { s_sum[t >> 5] = s; s_sq[t >> 5] = q; }
    __syncthreads();
    int h = t >> 6;
    float sum = s_sum[2*h] + s_sum[2*h+1];
    float sq  = s_sq [2*h] + s_sq [2*h+1];
    float mean = sum * (1.0f/64.0f);
    float var  = fmaxf(sq * (1.0f/64.0f) - mean*mean, 0.0f);
    float r    = (val - mean) / (sqrtf(var) * 16.0f);
    if (bx < 5 * DIM) g_Wbf[bx >> 8][t * DIM + (bx & 255)] = __float2bfloat16(r);
    else              g_b[bx - 5 * DIM][t] = r;
}

// ---------------------------------------------------------------------------
// PTX helpers (baseline PTX only: ldmatrix + mma.sync, sm_80+)
// ---------------------------------------------------------------------------
__device__ __forceinline__ uint32_t s2u(const void* p) {
    uint32_t a;
    asm("{ .reg .u64 t; cvta.to.shared.u64 t, %1; cvt.u32.u64 %0, t; }" : "=r"(a) : "l"(p));
    return a;
}
__device__ __forceinline__ void ldsm4(uint32_t* r, uint32_t a) {
    asm volatile("ldmatrix.sync.aligned.m8n8.x4.shared.b16 {%0,%1,%2,%3}, [%4];"
                 : "=r"(r[0]), "=r"(r[1]), "=r"(r[2]), "=r"(r[3]) : "r"(a));
}
__device__ __forceinline__ void ldsm2(uint32_t* r, uint32_t a) {
    asm volatile("ldmatrix.sync.aligned.m8n8.x2.shared.b16 {%0,%1}, [%2];"
                 : "=r"(r[0]), "=r"(r[1]) : "r"(a));
}
__device__ __forceinline__ void mma16816(float* d, const uint32_t* a, const uint32_t* b) {
    asm volatile("mma.sync.aligned.m16n8k16.row.col.f32.bf16.bf16.f32 "
                 "{%0,%1,%2,%3}, {%4,%5,%6,%7}, {%8,%9}, {%0,%1,%2,%3};"
                 : "+f"(d[0]), "+f"(d[1]), "+f"(d[2]), "+f"(d[3])
                 : "r"(a[0]), "r"(a[1]), "r"(a[2]), "r"(a[3]), "r"(b[0]), "r"(b[1]));
}
__device__ __forceinline__ uint32_t bfx2(float lo, float hi) {   // low half = lo
    uint32_t r;
    asm("cvt.rn.bf16x2.f32 %0, %1, %2;" : "=r"(r) : "f"(hi), "f"(lo));
    return r;
}

// ---------------------------------------------------------------------------
// smem layout (bytes). Activation tiles: 64 rows x 264 bf16, stride 528 B
// (16B-aligned, 4-bank shift per row -> conflict-free ldmatrix).
// P tiles: per head 64 x 72 bf16 (stride 144 B). VT: 256 x 72 bf16.
// ---------------------------------------------------------------------------
#define RST 260
#define SM_R    0        // 49*260*4 = 50960
#define SM_P    51072    // 36864 : x tile (64x264), later P tiles 4 x (64x72)
#define SM_Q    87936    // 33792 : Q tile, later x2 / t3 tile
#define SM_K    121728   // 33792 : K tile
#define SM_VT   155520   // 36864 : V^T 256 x 72
#define SM_BIAS 192384   // 5120  : biases fp32 [5][256]
#define SMEM_TOTAL 197504

// One 64x256x256 GEMM: warp computes m64 x n32 (n0 = warp*32).
// A from smem (stride 528), B from global W^T (u32 view, row = 128 u32).
__device__ __forceinline__ void mma_gemm(uint32_t aBase, const uint32_t* __restrict__ Wrow,
                                         float acc[4][4][4], uint32_t aoff)
{
    #pragma unroll
    for (int mf = 0; mf < 4; mf++)
        #pragma unroll
        for (int nf = 0; nf < 4; nf++)
            #pragma unroll
            for (int q = 0; q < 4; q++) acc[mf][nf][q] = 0.0f;

    #pragma unroll 4
    for (int ks = 0; ks < 16; ks++) {
        uint32_t a[4][4];
        #pragma unroll
        for (int mf = 0; mf < 4; mf++)
            ldsm4(a[mf], aBase + aoff + (uint32_t)(mf * 16 * 528 + ks * 32));
        #pragma unroll
        for (int nf = 0; nf < 4; nf++) {
            uint32_t b[2];
            b[0] = __ldg(Wrow + nf * 1024 + ks * 8);
            b[1] = __ldg(Wrow + nf * 1024 + ks * 8 + 4);
            #pragma unroll
            for (int mf = 0; mf < 4; mf++) mma16816(acc[mf][nf], a[mf], b);
        }
    }
}

__global__ __launch_bounds__(256, 1) void irmb_kernel(
    const float* __restrict__ x, float* __restrict__ out)
{
    extern __shared__ char sm[];
    const uint32_t sb = s2u(sm);
    const int tid = threadIdx.x, w = tid >> 5, lane = tid & 31;

    float* R = (float*)(sm + SM_R);
    float* sBias = (float*)(sm + SM_BIAS);

    // zero x/P buffer + VT, load biases
    {
        uint32_t* z = (uint32_t*)(sm + SM_P);
        for (int i = tid; i < 9216; i += 256) z[i] = 0;
        uint32_t* z2 = (uint32_t*)(sm + SM_VT);
        for (int i = tid; i < 9216; i += 256) z2[i] = 0;
        const float* gb = (const float*)g_b;
        for (int i = tid; i < 1280; i += 256) sBias[i] = gb[i];
    }
    const float* xb = x + (size_t)blockIdx.x * (NTOK * DIM);
    float* ob = out + (size_t)blockIdx.x * (NTOK * DIM);
    __syncthreads();

    for (int i = tid; i < NTOK * DIM; i += 256) {
        int r = i >> 8, c = i & 255;
        float v = xb[i];
        R[r * RST + c] = v;
        *(__nv_bfloat16*)(sm + SM_P + r * 528 + c * 2) = __float2bfloat16(v);
    }
    __syncthreads();

    // lane-mapping constants
    const int gq = lane >> 3, iq = lane & 7;
    const uint32_t aoff = (uint32_t)((iq + (gq & 1) * 8) * 528 + ((gq >> 1) * 8) * 2);
    const int r0 = lane >> 2, c0 = 2 * (lane & 3);
    const int n0 = w * 32;
    const uint32_t* Wbase = (const uint32_t*)g_Wbf;         // 32768 u32 per matrix
    const int wrow_off = (n0 + (lane >> 2)) * 128 + (lane & 3);

    float acc[4][4][4];

    // ---- Q ----
    mma_gemm(sb + SM_P, Wbase + wrow_off, acc, aoff);
    #pragma unroll
    for (int mf = 0; mf < 4; mf++)
        #pragma unroll
        for (int nf = 0; nf < 4; nf++)
            #pragma unroll
            for (int rr = 0; rr < 2; rr++) {
                int r = mf * 16 + r0 + rr * 8;
                int c = n0 + nf * 8 + c0;
                *(uint32_t*)(sm + SM_Q + r * 528 + c * 2) =
                    bfx2(acc[mf][nf][rr*2] + sBias[c], acc[mf][nf][rr*2+1] + sBias[c+1]);
            }

    // ---- K ----
    mma_gemm(sb + SM_P, Wbase + 32768 + wrow_off, acc, aoff);
    #pragma unroll
    for (int mf = 0; mf < 4; mf++)
        #pragma unroll
        for (int nf = 0; nf < 4; nf++)
            #pragma unroll
            for (int rr = 0; rr < 2; rr++) {
                int r = mf * 16 + r0 + rr * 8;
                int c = n0 + nf * 8 + c0;
                *(uint32_t*)(sm + SM_K + r * 528 + c * 2) =
                    bfx2(acc[mf][nf][rr*2] + sBias[256+c], acc[mf][nf][rr*2+1] + sBias[256+c+1]);
            }

    // ---- V (V' = (xWv+b)*0.1 + x*0.95 -> R, and V^T bf16) ----
    mma_gemm(sb + SM_P, Wbase + 2 * 32768 + wrow_off, acc, aoff);
    #pragma unroll
    for (int mf = 0; mf < 4; mf++)
        #pragma unroll
        for (int nf = 0; nf < 4; nf++)
            #pragma unroll
            for (int rr = 0; rr < 2; rr++) {
                int r = mf * 16 + r0 + rr * 8;
                if (r < NTOK) {
                    int c = n0 + nf * 8 + c0;
                    float v0 = (acc[mf][nf][rr*2]   + sBias[512+c])   * 0.1f + R[r*RST+c]   * 0.95f;
                    float v1 = (acc[mf][nf][rr*2+1] + sBias[512+c+1]) * 0.1f + R[r*RST+c+1] * 0.95f;
                    R[r*RST+c] = v0; R[r*RST+c+1] = v1;
                    *(__nv_bfloat16*)(sm + SM_VT + c * 144 + r * 2)       = __float2bfloat16(v0);
                    *(__nv_bfloat16*)(sm + SM_VT + (c + 1) * 144 + r * 2) = __float2bfloat16(v1);
                }
            }
    __syncthreads();

    // ---- scores + in-register softmax -> P (bf16, per-head tiles in SM_P) ----
    const int mfs = w & 3, hw = w >> 2;
    #pragma unroll
    for (int p = 0; p < 2; p++) {
        int h = 2 * p + hw;
        float sc[7][4];
        #pragma unroll
        for (int nf = 0; nf < 7; nf++)
            #pragma unroll
            for (int q = 0; q < 4; q++) sc[nf][q] = 0.0f;

        uint32_t qbase = sb + SM_Q + (uint32_t)(mfs * 16 * 528) + aoff + (uint32_t)(h * 128);
        uint32_t kb    = sb + SM_K + (uint32_t)((lane & 7) * 528) + (uint32_t)(h * 128)
                       + (uint32_t)(((lane >> 3) & 1) * 16);
        #pragma unroll
        for (int ks = 0; ks < 4; ks++) {
            uint32_t a[4];
            ldsm4(a, qbase + ks * 32);
            #pragma unroll
            for (int nf = 0; nf < 7; nf++) {
                uint32_t b[2];
                ldsm2(b, kb + (uint32_t)(nf * 8 * 528) + ks * 32);
                mma16816(sc[nf], a, b);
            }
        }
        #pragma unroll
        for (int half = 0; half < 2; half++) {
            int r = mfs * 16 + r0 + half * 8;
            float vv[14];
            float m = -1e30f;
            #pragma unroll
            for (int nf = 0; nf < 7; nf++)
                #pragma unroll
                for (int j = 0; j < 2; j++) {
                    int kk = nf * 8 + c0 + j;
                    float s = (kk < NTOK) ? sc[nf][half*2 + j] * 0.125f : -1e30f;
                    vv[nf*2 + j] = s;
                    m = fmaxf(m, s);
                }
            m = fmaxf(m, __shfl_xor_sync(0xFFFFFFFFu, m, 1));
            m = fmaxf(m, __shfl_xor_sync(0xFFFFFFFFu, m, 2));
            float sum = 0.0f;
            #pragma unroll
            for (int t = 0; t < 14; t++) {
                float e = (vv[t] > -1e29f) ? __expf(vv[t] - m) : 0.0f;
                vv[t] = e; sum += e;
            }
            sum += __shfl_xor_sync(0xFFFFFFFFu, sum, 1);
            sum += __shfl_xor_sync(0xFFFFFFFFu, sum, 2);
            float inv = 1.0f / sum;
            #pragma unroll
            for (int nf = 0; nf < 7; nf++) {
                uint32_t pk = (r < NTOK) ? bfx2(vv[nf*2] * inv, vv[nf*2+1] * inv) : 0u;
                *(uint32_t*)(sm + SM_P + h * 9216 + r * 144 + (nf * 8 + c0) * 2) = pk;
            }
        }
    }
    __syncthreads();

    // ---- PV: out = P @ V'  ; x2 = out*0.1 + R*0.95 -> R, bf16 tile in SM_Q ----
    {
        const int nfr = (w >> 2) * 4;
        const uint32_t poff = (uint32_t)((iq + (gq & 1) * 8) * 144 + ((gq >> 1) * 8) * 2);
        #pragma unroll
        for (int h = 0; h < 4; h++) {
            float pa[4][4];
            #pragma unroll
            for (int nf = 0; nf < 4; nf++)
                #pragma unroll
                for (int q = 0; q < 4; q++) pa[nf][q] = 0.0f;

            uint32_t pbase = sb + SM_P + (uint32_t)(h * 9216 + mfs * 16 * 144) + poff;
            uint32_t vb = sb + SM_VT + (uint32_t)((h * 64 + nfr * 8 + (lane & 7)) * 144)
                        + (uint32_t)(((lane >> 3) & 1) * 16);
            #pragma unroll
            for (int ks = 0; ks < 4; ks++) {
                uint32_t a[4];
                ldsm4(a, pbase + ks * 32);
                #pragma unroll
                for (int nf = 0; nf < 4; nf++) {
                    uint32_t b[2];
                    ldsm2(b, vb + (uint32_t)(nf * 8 * 144) + ks * 32);
                    mma16816(pa[nf], a, b);
                }
            }
            #pragma unroll
            for (int nf = 0; nf < 4; nf++)
                #pragma unroll
                for (int rr = 0; rr < 2; rr++) {
                    int r = mfs * 16 + r0 + rr * 8;
                    int c = h * 64 + nfr * 8 + nf * 8 + c0;
                    if (r < NTOK) {
                        float a0 = pa[nf][rr*2]   * 0.1f + R[r*RST+c]   * 0.95f;
                        float a1 = pa[nf][rr*2+1] * 0.1f + R[r*RST+c+1] * 0.95f;
                        R[r*RST+c] = a0; R[r*RST+c+1] = a1;
                        *(uint32_t*)(sm + SM_Q + r * 528 + c * 2) = bfx2(a0, a1);
                    } else {
                        *(uint32_t*)(sm + SM_Q + r * 528 + c * 2) = 0u;
                    }
                }
        }
    }
    __syncthreads();

    // ---- FFN in: t2 = (x2 Wfi + b)*0.1 + x2*0.95 ; t3 = (sig(t2)-0.5)*0.1 + t2*0.95 ----
    mma_gemm(sb + SM_Q, Wbase + 3 * 32768 + wrow_off, acc, aoff);
    __syncthreads();           // all reads of x2 tile done before overwrite
    #pragma unroll
    for (int mf = 0; mf < 4; mf++)
        #pragma unroll
        for (int nf = 0; nf < 4; nf++)
            #pragma unroll
            for (int rr = 0; rr < 2; rr++) {
                int r = mf * 16 + r0 + rr * 8;
                int c = n0 + nf * 8 + c0;
                if (r < NTOK) {
                    float t2a = (acc[mf][nf][rr*2]   + sBias[768+c])   * 0.1f + R[r*RST+c]   * 0.95f;
                    float t2b = (acc[mf][nf][rr*2+1] + sBias[768+c+1]) * 0.1f + R[r*RST+c+1] * 0.95f;
                    float t3a = (1.0f/(1.0f + __expf(-t2a)) - 0.5f) * 0.1f + t2a * 0.95f;
                    float t3b = (1.0f/(1.0f + __expf(-t2b)) - 0.5f) * 0.1f + t2b * 0.95f;
                    R[r*RST+c] = t3a; R[r*RST+c+1] = t3b;
                    *(uint32_t*)(sm + SM_Q + r * 528 + c * 2) = bfx2(t3a, t3b);
                } else {
                    *(uint32_t*)(sm + SM_Q + r * 528 + c * 2) = 0u;
                }
            }
    __syncthreads();

    // ---- FFN out: out = (t3 Wfo + b)*0.1 + t3*0.95 ----
    mma_gemm(sb + SM_Q, Wbase + 4 * 32768 + wrow_off, acc, aoff);
    #pragma unroll
    for (int mf = 0; mf < 4; mf++)
        #pragma unroll
        for (int nf = 0; nf < 4; nf++)
            #pragma unroll
            for (int rr = 0; rr < 2; rr++) {
                int r = mf * 16 + r0 + rr * 8;
                if (r < NTOK) {
                    int c = n0 + nf * 8 + c0;
                    ob[r*DIM + c]   = (acc[mf][nf][rr*2]   + sBias[1024+c])   * 0.1f + R[r*RST+c]   * 0.95f;
                    ob[r*DIM + c+1] = (acc[mf][nf][rr*2+1] + sBias[1024+c+1]) * 0.1f + R[r*RST+c+1] * 0.95f;
                }
            }
}

// ---------------------------------------------------------------------------
extern "C" void kernel_launch(void* const* d_in, const int* in_sizes, int n_in,
                              void* d_out, int out_size)
{
    std_kernel<<<5 * DIM + 5, 256>>>(
        (const float*)d_in[1], (const float*)d_in[2],
        (const float*)d_in[3], (const float*)d_in[4],
        (const float*)d_in[5], (const float*)d_in[6],
        (const float*)d_in[7], (const float*)d_in[8],
        (const float*)d_in[9], (const float*)d_in[10]);

    cudaFuncSetAttribute(irmb_kernel,
                         cudaFuncAttributeMaxDynamicSharedMemorySize, SMEM_TOTAL);
    irmb_kernel<<<NB, 256, SMEM_TOTAL>>>((const float*)d_in[0], (float*)d_out);
}

// round 7
// speedup vs baseline: 6.2401x; 1.4662x over previous
#include <cuda_runtime.h>
#include <cuda_bf16.h>
#include <math.h>
#include <stdint.h>

#define DIM  256
#define NH   4
#define HC   64
#define NTOK 49
#define NB   4096

// Standardized weights in mma-FRAGMENT order:
// [matrix][nblk(32)][ks(16)][lane(32)][2 x u32(bf16x2)]  = 128KB per matrix.
// For col c, k: nblk=c>>3, lane=(c&7)*4+((k>>1)&3), half=(k>>3)&1, par=k&1.
__device__ __align__(16) __nv_bfloat16 g_Wbf[5][DIM * DIM];
__device__ float g_b[5][DIM];

#define W_MAT_STRIDE 16384   // uint2 per 256x256 bf16 matrix

// ---------------------------------------------------------------------------
// Prologue: weight standardization -> fragment-ordered bf16
// ---------------------------------------------------------------------------
__global__ __launch_bounds__(256) void std_kernel(
    const float* __restrict__ qw, const float* __restrict__ qb,
    const float* __restrict__ kw, const float* __restrict__ kb,
    const float* __restrict__ vw, const float* __restrict__ vb,
    const float* __restrict__ fiw, const float* __restrict__ fib,
    const float* __restrict__ fow, const float* __restrict__ fob)
{
    const float* wptr[5] = {qw, kw, vw, fiw, fow};
    const float* bptr[5] = {qb, kb, vb, fib, fob};
    __shared__ float s_sum[8], s_sq[8];
    int bx = blockIdx.x, t = threadIdx.x;

    float val;
    if (bx < 5 * DIM) val = wptr[bx >> 8][(bx & 255) * DIM + t];
    else              val = bptr[bx - 5 * DIM][t];

    float s = val, q = val * val;
    #pragma unroll
    for (int o = 16; o > 0; o >>= 1) {
        s += __shfl_xor_sync(0xFFFFFFFFu, s, o);
        q += __shfl_xor_sync(0xFFFFFFFFu, q, o);
    }
    if ((t & 31) == 0) { s_sum[t >> 5] = s; s_sq[t >> 5] = q; }
    __syncthreads();
    int h = t >> 6;
    float sum = s_sum[2*h] + s_sum[2*h+1];
    float sq  = s_sq [2*h] + s_sq [2*h+1];
    float mean = sum * (1.0f/64.0f);
    float var  = fmaxf(sq * (1.0f/64.0f) - mean*mean, 0.0f);
    float r    = (val - mean) / (sqrtf(var) * 16.0f);

    if (bx < 5 * DIM) {
        int m = bx >> 8, k = bx & 255, c = t;
        int ks   = k >> 4;
        int half = (k >> 3) & 1;
        int pos2 = (k >> 1) & 3;
        int par  = k & 1;
        int lane = (c & 7) * 4 + pos2;
        int nblk = c >> 3;
        size_t u32idx = (size_t)(((nblk * 16 + ks) * 32 + lane) * 2 + half);
        ((__nv_bfloat16*)g_Wbf)[(size_t)m * DIM * DIM + u32idx * 2 + par] =
            __float2bfloat16(r);
    } else {
        g_b[bx - 5 * DIM][t] = r;
    }
}

// ---------------------------------------------------------------------------
// PTX helpers (baseline PTX only: ldmatrix + mma.sync, sm_80+)
// ---------------------------------------------------------------------------
__device__ __forceinline__ uint32_t s2u(const void* p) {
    uint32_t a;
    asm("{ .reg .u64 t; cvta.to.shared.u64 t, %1; cvt.u32.u64 %0, t; }" : "=r"(a) : "l"(p));
    return a;
}
__device__ __forceinline__ void ldsm4(uint32_t* r, uint32_t a) {
    asm volatile("ldmatrix.sync.aligned.m8n8.x4.shared.b16 {%0,%1,%2,%3}, [%4];"
                 : "=r"(r[0]), "=r"(r[1]), "=r"(r[2]), "=r"(r[3]) : "r"(a));
}
__device__ __forceinline__ void ldsm2(uint32_t* r, uint32_t a) {
    asm volatile("ldmatrix.sync.aligned.m8n8.x2.shared.b16 {%0,%1}, [%2];"
                 : "=r"(r[0]), "=r"(r[1]) : "r"(a));
}
__device__ __forceinline__ void mma16816(float* d, const uint32_t* a, const uint32_t* b) {
    asm volatile("mma.sync.aligned.m16n8k16.row.col.f32.bf16.bf16.f32 "
                 "{%0,%1,%2,%3}, {%4,%5,%6,%7}, {%8,%9}, {%0,%1,%2,%3};"
                 : "+f"(d[0]), "+f"(d[1]), "+f"(d[2]), "+f"(d[3])
                 : "r"(a[0]), "r"(a[1]), "r"(a[2]), "r"(a[3]), "r"(b[0]), "r"(b[1]));
}
__device__ __forceinline__ uint32_t bfx2(float lo, float hi) {   // low half = lo
    uint32_t r;
    asm("cvt.rn.bf16x2.f32 %0, %1, %2;" : "=r"(r) : "f"(hi), "f"(lo));
    return r;
}

// ---------------------------------------------------------------------------
// smem layout (bytes). Activation tiles: 64 rows x 264 bf16, stride 528 B.
// P tiles: per head 64 x 72 bf16 (stride 144 B). VT: 256 x 72 bf16.
// ---------------------------------------------------------------------------
#define RST 260
#define SM_R    0        // 49*260*4 = 50960
#define SM_P    51072    // 36864 : x tile (64x264), later P tiles 4 x (64x72)
#define SM_Q    87936    // 33792 : Q tile, later x2 / t3 tile
#define SM_K    121728   // 33792 : K tile
#define SM_VT   155520   // 36864 : V^T 256 x 72
#define SM_BIAS 192384   // 5120  : biases fp32 [5][256]
#define SMEM_TOTAL 197504

// One 64x256x256 GEMM: warp computes m64 x n32.
// A from smem (stride 528); B via coalesced LDG.64 from fragment-ordered W.
__device__ __forceinline__ void mma_gemm(uint32_t aBase, const uint2* __restrict__ Wf,
                                         float acc[4][4][4], uint32_t aoff)
{
    #pragma unroll
    for (int mf = 0; mf < 4; mf++)
        #pragma unroll
        for (int nf = 0; nf < 4; nf++)
            #pragma unroll
            for (int q = 0; q < 4; q++) acc[mf][nf][q] = 0.0f;

    #pragma unroll 4
    for (int ks = 0; ks < 16; ks++) {
        uint32_t a[4][4];
        #pragma unroll
        for (int mf = 0; mf < 4; mf++)
            ldsm4(a[mf], aBase + aoff + (uint32_t)(mf * 16 * 528 + ks * 32));
        #pragma unroll
        for (int nf = 0; nf < 4; nf++) {
            uint2 b2 = __ldg(Wf + (nf * 16 + ks) * 32);
            uint32_t b[2] = { b2.x, b2.y };
            #pragma unroll
            for (int mf = 0; mf < 4; mf++) mma16816(acc[mf][nf], a[mf], b);
        }
    }
}

__global__ __launch_bounds__(256, 1) void irmb_kernel(
    const float* __restrict__ x, float* __restrict__ out)
{
    extern __shared__ char sm[];
    const uint32_t sb = s2u(sm);
    const int tid = threadIdx.x, w = tid >> 5, lane = tid & 31;

    float* R = (float*)(sm + SM_R);
    float* sBias = (float*)(sm + SM_BIAS);

    // zero x/P buffer + VT, load biases
    {
        uint32_t* z = (uint32_t*)(sm + SM_P);
        for (int i = tid; i < 9216; i += 256) z[i] = 0;
        uint32_t* z2 = (uint32_t*)(sm + SM_VT);
        for (int i = tid; i < 9216; i += 256) z2[i] = 0;
        const float* gb = (const float*)g_b;
        for (int i = tid; i < 1280; i += 256) sBias[i] = gb[i];
    }
    const float* xb = x + (size_t)blockIdx.x * (NTOK * DIM);
    float* ob = out + (size_t)blockIdx.x * (NTOK * DIM);
    __syncthreads();

    for (int i = tid; i < NTOK * DIM; i += 256) {
        int r = i >> 8, c = i & 255;
        float v = xb[i];
        R[r * RST + c] = v;
        *(__nv_bfloat16*)(sm + SM_P + r * 528 + c * 2) = __float2bfloat16(v);
    }
    __syncthreads();

    // lane-mapping constants
    const int gq = lane >> 3, iq = lane & 7;
    const uint32_t aoff = (uint32_t)((iq + (gq & 1) * 8) * 528 + ((gq >> 1) * 8) * 2);
    const int r0 = lane >> 2, c0 = 2 * (lane & 3);
    const int n0 = w * 32;
    const uint2* Wfb = (const uint2*)g_Wbf;       // W_MAT_STRIDE uint2 per matrix
    const int wfoff = w * 4 * 16 * 32 + lane;     // uint2 units

    float acc[4][4][4];

    // ---- Q ----
    mma_gemm(sb + SM_P, Wfb + wfoff, acc, aoff);
    #pragma unroll
    for (int mf = 0; mf < 4; mf++)
        #pragma unroll
        for (int nf = 0; nf < 4; nf++)
            #pragma unroll
            for (int rr = 0; rr < 2; rr++) {
                int r = mf * 16 + r0 + rr * 8;
                int c = n0 + nf * 8 + c0;
                *(uint32_t*)(sm + SM_Q + r * 528 + c * 2) =
                    bfx2(acc[mf][nf][rr*2] + sBias[c], acc[mf][nf][rr*2+1] + sBias[c+1]);
            }

    // ---- K ----
    mma_gemm(sb + SM_P, Wfb + W_MAT_STRIDE + wfoff, acc, aoff);
    #pragma unroll
    for (int mf = 0; mf < 4; mf++)
        #pragma unroll
        for (int nf = 0; nf < 4; nf++)
            #pragma unroll
            for (int rr = 0; rr < 2; rr++) {
                int r = mf * 16 + r0 + rr * 8;
                int c = n0 + nf * 8 + c0;
                *(uint32_t*)(sm + SM_K + r * 528 + c * 2) =
                    bfx2(acc[mf][nf][rr*2] + sBias[256+c], acc[mf][nf][rr*2+1] + sBias[256+c+1]);
            }

    // ---- V (V' = (xWv+b)*0.1 + x*0.95 -> R, and V^T bf16) ----
    mma_gemm(sb + SM_P, Wfb + 2 * W_MAT_STRIDE + wfoff, acc, aoff);
    #pragma unroll
    for (int mf = 0; mf < 4; mf++)
        #pragma unroll
        for (int nf = 0; nf < 4; nf++)
            #pragma unroll
            for (int rr = 0; rr < 2; rr++) {
                int r = mf * 16 + r0 + rr * 8;
                if (r < NTOK) {
                    int c = n0 + nf * 8 + c0;
                    float v0 = (acc[mf][nf][rr*2]   + sBias[512+c])   * 0.1f + R[r*RST+c]   * 0.95f;
                    float v1 = (acc[mf][nf][rr*2+1] + sBias[512+c+1]) * 0.1f + R[r*RST+c+1] * 0.95f;
                    R[r*RST+c] = v0; R[r*RST+c+1] = v1;
                    *(__nv_bfloat16*)(sm + SM_VT + c * 144 + r * 2)       = __float2bfloat16(v0);
                    *(__nv_bfloat16*)(sm + SM_VT + (c + 1) * 144 + r * 2) = __float2bfloat16(v1);
                }
            }
    __syncthreads();

    // ---- scores + in-register softmax -> P (bf16, per-head tiles in SM_P) ----
    const int mfs = w & 3, hw = w >> 2;
    #pragma unroll
    for (int p = 0; p < 2; p++) {
        int h = 2 * p + hw;
        float sc[7][4];
        #pragma unroll
        for (int nf = 0; nf < 7; nf++)
            #pragma unroll
            for (int q = 0; q < 4; q++) sc[nf][q] = 0.0f;

        uint32_t qbase = sb + SM_Q + (uint32_t)(mfs * 16 * 528) + aoff + (uint32_t)(h * 128);
        uint32_t kb    = sb + SM_K + (uint32_t)((lane & 7) * 528) + (uint32_t)(h * 128)
                       + (uint32_t)(((lane >> 3) & 1) * 16);
        #pragma unroll
        for (int ks = 0; ks < 4; ks++) {
            uint32_t a[4];
            ldsm4(a, qbase + ks * 32);
            #pragma unroll
            for (int nf = 0; nf < 7; nf++) {
                uint32_t b[2];
                ldsm2(b, kb + (uint32_t)(nf * 8 * 528) + ks * 32);
                mma16816(sc[nf], a, b);
            }
        }
        #pragma unroll
        for (int half = 0; half < 2; half++) {
            int r = mfs * 16 + r0 + half * 8;
            float vv[14];
            float m = -1e30f;
            #pragma unroll
            for (int nf = 0; nf < 7; nf++)
                #pragma unroll
                for (int j = 0; j < 2; j++) {
                    int kk = nf * 8 + c0 + j;
                    float s = (kk < NTOK) ? sc[nf][half*2 + j] * 0.125f : -1e30f;
                    vv[nf*2 + j] = s;
                    m = fmaxf(m, s);
                }
            m = fmaxf(m, __shfl_xor_sync(0xFFFFFFFFu, m, 1));
            m = fmaxf(m, __shfl_xor_sync(0xFFFFFFFFu, m, 2));
            float sum = 0.0f;
            #pragma unroll
            for (int t = 0; t < 14; t++) {
                float e = (vv[t] > -1e29f) ? __expf(vv[t] - m) : 0.0f;
                vv[t] = e; sum += e;
            }
            sum += __shfl_xor_sync(0xFFFFFFFFu, sum, 1);
            sum += __shfl_xor_sync(0xFFFFFFFFu, sum, 2);
            float inv = 1.0f / sum;
            #pragma unroll
            for (int nf = 0; nf < 7; nf++) {
                uint32_t pk = (r < NTOK) ? bfx2(vv[nf*2] * inv, vv[nf*2+1] * inv) : 0u;
                *(uint32_t*)(sm + SM_P + h * 9216 + r * 144 + (nf * 8 + c0) * 2) = pk;
            }
        }
    }
    __syncthreads();

    // ---- PV: out = P @ V'  ; x2 = out*0.1 + R*0.95 -> R, bf16 tile in SM_Q ----
    {
        const int nfr = (w >> 2) * 4;
        const uint32_t poff = (uint32_t)((iq + (gq & 1) * 8) * 144 + ((gq >> 1) * 8) * 2);
        #pragma unroll
        for (int h = 0; h < 4; h++) {
            float pa[4][4];
            #pragma unroll
            for (int nf = 0; nf < 4; nf++)
                #pragma unroll
                for (int q = 0; q < 4; q++) pa[nf][q] = 0.0f;

            uint32_t pbase = sb + SM_P + (uint32_t)(h * 9216 + mfs * 16 * 144) + poff;
            uint32_t vb = sb + SM_VT + (uint32_t)((h * 64 + nfr * 8 + (lane & 7)) * 144)
                        + (uint32_t)(((lane >> 3) & 1) * 16);
            #pragma unroll
            for (int ks = 0; ks < 4; ks++) {
                uint32_t a[4];
                ldsm4(a, pbase + ks * 32);
                #pragma unroll
                for (int nf = 0; nf < 4; nf++) {
                    uint32_t b[2];
                    ldsm2(b, vb + (uint32_t)(nf * 8 * 144) + ks * 32);
                    mma16816(pa[nf], a, b);
                }
            }
            #pragma unroll
            for (int nf = 0; nf < 4; nf++)
                #pragma unroll
                for (int rr = 0; rr < 2; rr++) {
                    int r = mfs * 16 + r0 + rr * 8;
                    int c = h * 64 + nfr * 8 + nf * 8 + c0;
                    if (r < NTOK) {
                        float a0 = pa[nf][rr*2]   * 0.1f + R[r*RST+c]   * 0.95f;
                        float a1 = pa[nf][rr*2+1] * 0.1f + R[r*RST+c+1] * 0.95f;
                        R[r*RST+c] = a0; R[r*RST+c+1] = a1;
                        *(uint32_t*)(sm + SM_Q + r * 528 + c * 2) = bfx2(a0, a1);
                    } else {
                        *(uint32_t*)(sm + SM_Q + r * 528 + c * 2) = 0u;
                    }
                }
        }
    }
    __syncthreads();

    // ---- FFN in: t2 = (x2 Wfi + b)*0.1 + x2*0.95 ; t3 = (sig(t2)-0.5)*0.1 + t2*0.95 ----
    mma_gemm(sb + SM_Q, Wfb + 3 * W_MAT_STRIDE + wfoff, acc, aoff);
    __syncthreads();           // all reads of x2 tile done before overwrite
    #pragma unroll
    for (int mf = 0; mf < 4; mf++)
        #pragma unroll
        for (int nf = 0; nf < 4; nf++)
            #pragma unroll
            for (int rr = 0; rr < 2; rr++) {
                int r = mf * 16 + r0 + rr * 8;
                int c = n0 + nf * 8 + c0;
                if (r < NTOK) {
                    float t2a = (acc[mf][nf][rr*2]   + sBias[768+c])   * 0.1f + R[r*RST+c]   * 0.95f;
                    float t2b = (acc[mf][nf][rr*2+1] + sBias[768+c+1]) * 0.1f + R[r*RST+c+1] * 0.95f;
                    float t3a = (1.0f/(1.0f + __expf(-t2a)) - 0.5f) * 0.1f + t2a * 0.95f;
                    float t3b = (1.0f/(1.0f + __expf(-t2b)) - 0.5f) * 0.1f + t2b * 0.95f;
                    R[r*RST+c] = t3a; R[r*RST+c+1] = t3b;
                    *(uint32_t*)(sm + SM_Q + r * 528 + c * 2) = bfx2(t3a, t3b);
                } else {
                    *(uint32_t*)(sm + SM_Q + r * 528 + c * 2) = 0u;
                }
            }
    __syncthreads();

    // ---- FFN out: out = (t3 Wfo + b)*0.1 + t3*0.95 ----
    mma_gemm(sb + SM_Q, Wfb + 4 * W_MAT_STRIDE + wfoff, acc, aoff);
    #pragma unroll
    for (int mf = 0; mf < 4; mf++)
        #pragma unroll
        for (int nf = 0; nf < 4; nf++)
            #pragma unroll
            for (int rr = 0; rr < 2; rr++) {
                int r = mf * 16 + r0 + rr * 8;
                if (r < NTOK) {
                    int c = n0 + nf * 8 + c0;
                    ob[r*DIM + c]   = (acc[mf][nf][rr*2]   + sBias[1024+c])   * 0.1f + R[r*RST+c]   * 0.95f;
                    ob[r*DIM + c+1] = (acc[mf][nf][rr*2+1] + sBias[1024+c+1]) * 0.1f + R[r*RST+c+1] * 0.95f;
                }
            }
}

// ---------------------------------------------------------------------------
extern "C" void kernel_launch(void* const* d_in, const int* in_sizes, int n_in,
                              void* d_out, int out_size)
{
    std_kernel<<<5 * DIM + 5, 256>>>(
        (const float*)d_in[1], (const float*)d_in[2],
        (const float*)d_in[3], (const float*)d_in[4],
        (const float*)d_in[5], (const float*)d_in[6],
        (const float*)d_in[7], (const float*)d_in[8],
        (const float*)d_in[9], (const float*)d_in[10]);

    cudaFuncSetAttribute(irmb_kernel,
                         cudaFuncAttributeMaxDynamicSharedMemorySize, SMEM_TOTAL);
    irmb_kernel<<<NB, 256, SMEM_TOTAL>>>((const float*)d_in[0], (float*)d_out);
}